// round 1
// baseline (speedup 1.0000x reference)
#include <cuda_runtime.h>
#include <cuda_fp16.h>
#include <mma.h>

using namespace nvcuda;

#define B_    8
#define CIN   320
#define COUT  320
#define H_    64
#define W_    64
#define KTOT  2880   // CIN * 9

// Scratch (allocation-free rule: __device__ globals)
__device__ __align__(16) __half g_xq[(size_t)B_ * CIN * H_ * W_];  // quantized-shifted activations, fp16
__device__ __align__(16) __half g_wh[(size_t)COUT * KTOT];         // weights as fp16

// ---------------------------------------------------------------------------
// Prep 1: x_shift = clip(round(x*inv) + zp, -128, 127) - zp   (fp16, exact ints)
// ---------------------------------------------------------------------------
__global__ void quant_kernel(const float* __restrict__ x,
                             const float* __restrict__ inv_p,
                             const float* __restrict__ zp_p,
                             int n4)
{
    const float inv = inv_p[0];
    const float zp  = zp_p[0];
    int i = blockIdx.x * blockDim.x + threadIdx.x;
    if (i >= n4) return;
    float4 v = reinterpret_cast<const float4*>(x)[i];
    float r0 = fminf(fmaxf(rintf(v.x * inv) + zp, -128.f), 127.f) - zp;
    float r1 = fminf(fmaxf(rintf(v.y * inv) + zp, -128.f), 127.f) - zp;
    float r2 = fminf(fmaxf(rintf(v.z * inv) + zp, -128.f), 127.f) - zp;
    float r3 = fminf(fmaxf(rintf(v.w * inv) + zp, -128.f), 127.f) - zp;
    __half2 h01 = __floats2half2_rn(r0, r1);
    __half2 h23 = __floats2half2_rn(r2, r3);
    uint2 pk;
    pk.x = *reinterpret_cast<unsigned*>(&h01);
    pk.y = *reinterpret_cast<unsigned*>(&h23);
    reinterpret_cast<uint2*>(g_xq)[i] = pk;
}

// ---------------------------------------------------------------------------
// Prep 2: weights int32 -> fp16 (values in [-128,127], exact)
// ---------------------------------------------------------------------------
__global__ void wconv_kernel(const int* __restrict__ w, int n)
{
    int i = blockIdx.x * blockDim.x + threadIdx.x;
    if (i < n) g_wh[i] = __int2half_rn(w[i]);
}

// ---------------------------------------------------------------------------
// Implicit GEMM conv: out[o, (b,h,w)] = scale[o] * sum_k W[o,k] * X[k,(b,h,w)] + bias[o]
//   M = COUT (320), N = B*H*W (32768), K = 2880
//   BM = BN = 64, BK = 32, 4 warps (2x2), each warp 32x32 via 2x2 wmma frags.
//   blockIdx.x = b*64 + h   (one output row of one image -> coalesced, simple borders)
//   blockIdx.y = m tile (0..4)
// ---------------------------------------------------------------------------
#define BM 64
#define BN 64
#define BK 32
#define APAD 8   // -> ld 40 halfs (80B rows, 16B-aligned)
#define BPAD 8   // -> ld 72 halfs
#define CPAD 8   // -> ld 72 floats

__global__ __launch_bounds__(128, 4)
void conv_gemm_kernel(const float* __restrict__ scale,
                      const float* __restrict__ bias,
                      float* __restrict__ out)
{
    __shared__ __align__(16) __half As[BM][BK + APAD];   // [m][k]
    __shared__ __align__(16) __half Bs[BK][BN + BPAD];   // [k][n]
    __shared__ __align__(16) float  Cs[BM][BN + CPAD];

    const int tid  = threadIdx.x;          // 0..127
    const int warp = tid >> 5;
    const int wm   = (warp >> 1) * 32;     // warp row offset in tile (0/32)
    const int wn   = (warp & 1) * 32;      // warp col offset (0/32)

    const int ntile = blockIdx.x;          // 0..511
    const int b = ntile >> 6;              // image
    const int h = ntile & 63;              // output row
    const int m0 = blockIdx.y * BM;

    wmma::fragment<wmma::accumulator, 16, 16, 16, float> acc[2][2];
#pragma unroll
    for (int i = 0; i < 2; i++)
#pragma unroll
        for (int j = 0; j < 2; j++)
            wmma::fill_fragment(acc[i][j], 0.0f);

    // B-tile load mapping: thread t -> k row = t>>2, 16 consecutive n starting at (t&3)*16
    const int bk  = tid >> 2;
    const int bn0 = (tid & 3) * 16;

    for (int k0 = 0; k0 < KTOT; k0 += BK) {
        // ---- load A tile: 64x32 halfs, vectorized 8-half (16B) loads ----
#pragma unroll
        for (int v = 0; v < 2; v++) {
            int idx = tid + v * 128;            // 0..255
            int row = idx >> 2;
            int col = (idx & 3) * 8;
            const uint4* gp = reinterpret_cast<const uint4*>(
                g_wh + (size_t)(m0 + row) * KTOT + k0 + col);
            *reinterpret_cast<uint4*>(&As[row][col]) = *gp;
        }

        // ---- load B tile: im2col on the fly ----
        {
            int kg = k0 + bk;
            int ci = kg / 9;
            int rr = kg - ci * 9;
            int kh = rr / 3;
            int kw = rr - kh * 3;
            int ih = h + kh - 1;
            bool rowok = (unsigned)ih < (unsigned)H_;
            const __half* src = g_xq + (((size_t)b * CIN + ci) * H_ + (rowok ? ih : 0)) * W_;
#pragma unroll
            for (int j = 0; j < 16; j++) {
                int n  = bn0 + j;
                int iw = n + kw - 1;
                __half val = (rowok && (unsigned)iw < (unsigned)W_) ? src[iw] : __half(0.0f);
                Bs[bk][n] = val;
            }
        }

        __syncthreads();

        // ---- compute: 2 k-steps of 16 ----
#pragma unroll
        for (int kk = 0; kk < BK; kk += 16) {
            wmma::fragment<wmma::matrix_a, 16, 16, 16, __half, wmma::row_major> af[2];
            wmma::fragment<wmma::matrix_b, 16, 16, 16, __half, wmma::row_major> bf[2];
#pragma unroll
            for (int i = 0; i < 2; i++)
                wmma::load_matrix_sync(af[i], &As[wm + 16 * i][kk], BK + APAD);
#pragma unroll
            for (int j = 0; j < 2; j++)
                wmma::load_matrix_sync(bf[j], &Bs[kk][wn + 16 * j], BN + BPAD);
#pragma unroll
            for (int i = 0; i < 2; i++)
#pragma unroll
                for (int j = 0; j < 2; j++)
                    wmma::mma_sync(acc[i][j], af[i], bf[j], acc[i][j]);
        }

        __syncthreads();
    }

    // ---- store accumulators to smem, then scale/bias epilogue ----
#pragma unroll
    for (int i = 0; i < 2; i++)
#pragma unroll
        for (int j = 0; j < 2; j++)
            wmma::store_matrix_sync(&Cs[wm + 16 * i][wn + 16 * j], acc[i][j],
                                    BN + CPAD, wmma::mem_row_major);
    __syncthreads();

    const int w  = tid & 63;          // output column
    const int r0 = tid >> 6;          // 0/1
#pragma unroll
    for (int r = 0; r < 32; r++) {
        int ol = r0 + r * 2;          // 0..63
        int o  = m0 + ol;
        float s  = scale[o];
        float bb = bias[o];
        out[(((size_t)b * COUT + o) * H_ + h) * W_ + w] = s * Cs[ol][w] + bb;
    }
}

// ---------------------------------------------------------------------------
// Launch
// Inputs (metadata order):
//   0: x                  f32  [8,320,64,64]
//   1: weight_int         i32  [320,320,3,3]
//   2: weight_sum_by_ic   f32  [320,1,3,3]   (unused: folded via x_shift)
//   3: scale              f32  [320]
//   4: act_scales_inv     f32  [1]
//   5: act_zero_points    f32  [1]
//   6: bias               f32  [320]
// Output: f32 [8,320,64,64]
// ---------------------------------------------------------------------------
extern "C" void kernel_launch(void* const* d_in, const int* in_sizes, int n_in,
                              void* d_out, int out_size)
{
    const float* x    = (const float*)d_in[0];
    const int*   wint = (const int*)  d_in[1];
    const float* scl  = (const float*)d_in[3];
    const float* inv  = (const float*)d_in[4];
    const float* zp   = (const float*)d_in[5];
    const float* bias = (const float*)d_in[6];
    float* out = (float*)d_out;

    // Prep: quantize activations (vectorized by 4)
    {
        int n  = B_ * CIN * H_ * W_;   // 10,485,760 (divisible by 4)
        int n4 = n / 4;
        int threads = 256;
        int blocks  = (n4 + threads - 1) / threads;
        quant_kernel<<<blocks, threads>>>(x, inv, zp, n4);
    }
    // Prep: convert weights
    {
        int n = COUT * KTOT;           // 921,600
        int threads = 256;
        int blocks  = (n + threads - 1) / threads;
        wconv_kernel<<<blocks, threads>>>(wint, n);
    }
    // Main implicit GEMM
    {
        dim3 grid(B_ * H_, COUT / BM); // (512, 5)
        conv_gemm_kernel<<<grid, 128>>>(scl, bias, out);
    }
}

// round 2
// speedup vs baseline: 2.0782x; 2.0782x over previous
#include <cuda_runtime.h>
#include <cuda_fp16.h>
#include <mma.h>
#include <cstdint>

using namespace nvcuda;

#define B_    8
#define CIN   320
#define COUT  320
#define H_    64
#define W_    64
#define KTOT  2880          // CIN * 9
#define BM    160
#define BN    64
#define BK    32
#define NK    (KTOT / BK)   // 90
#define NTHREADS 320

// Scratch (__device__ globals; no runtime allocation allowed)
// g_xq3[b][ci][h][kw][n] = x_shift[b,ci,h, n+kw-1]   (0 outside borders), fp16
__device__ __align__(16) __half g_xq3[(size_t)B_ * CIN * H_ * 3 * W_];   // 62.9 MB
__device__ __align__(16) __half g_wh[(size_t)COUT * KTOT];               // 1.8 MB

// ---------------------------------------------------------------------------
// cp.async helpers
// ---------------------------------------------------------------------------
__device__ __forceinline__ void cp_async16(uint32_t dst_smem, const void* src, int src_bytes) {
    asm volatile("cp.async.cg.shared.global [%0], [%1], 16, %2;\n"
                 :: "r"(dst_smem), "l"(src), "r"(src_bytes));
}
__device__ __forceinline__ void cp_commit() {
    asm volatile("cp.async.commit_group;\n" ::: "memory");
}
__device__ __forceinline__ void cp_wait0() {
    asm volatile("cp.async.wait_group 0;\n" ::: "memory");
}

// ---------------------------------------------------------------------------
// Prep 1: quantize + pre-shift. One warp per (b,ci,h) row.
//   lane loads x[2l..2l+1]; computes clipped-shifted ints in fp16;
//   writes 3 shifted copies (kw = 0,1,2) with zero borders.
// ---------------------------------------------------------------------------
__global__ void quant_kernel(const float* __restrict__ x,
                             const float* __restrict__ inv_p,
                             const float* __restrict__ zp_p)
{
    const float inv = inv_p[0];
    const float zp  = zp_p[0];
    int warp = (blockIdx.x * blockDim.x + threadIdx.x) >> 5;
    int lane = threadIdx.x & 31;
    if (warp >= B_ * CIN * H_) return;

    float2 v = reinterpret_cast<const float2*>(x + (size_t)warp * W_)[lane];
    float r0 = fminf(fmaxf(rintf(v.x * inv) + zp, -128.f), 127.f) - zp;
    float r1 = fminf(fmaxf(rintf(v.y * inv) + zp, -128.f), 127.f) - zp;
    __half2 h01 = __floats2half2_rn(r0, r1);
    uint32_t r = *reinterpret_cast<uint32_t*>(&h01);   // low = x[2l], high = x[2l+1]

    uint32_t prev = __shfl_up_sync(0xffffffffu, r, 1);
    uint32_t next = __shfl_down_sync(0xffffffffu, r, 1);
    if (lane == 0)  prev = 0;
    if (lane == 31) next = 0;
    uint32_t v0 = (prev >> 16) | (r << 16);   // (x[2l-1], x[2l])   -> kw=0
    uint32_t v2 = (r >> 16) | (next << 16);   // (x[2l+1], x[2l+2]) -> kw=2

    uint32_t* g32 = reinterpret_cast<uint32_t*>(g_xq3);
    size_t base = (size_t)warp * 96 + lane;   // 3*64 halfs = 96 u32 per row
    g32[base]      = v0;
    g32[base + 32] = r;
    g32[base + 64] = v2;
}

// ---------------------------------------------------------------------------
// Prep 2: weights int32 -> fp16
// ---------------------------------------------------------------------------
__global__ void wconv_kernel(const int* __restrict__ w, int n)
{
    int i = blockIdx.x * blockDim.x + threadIdx.x;
    if (i < n) g_wh[i] = __int2half_rn(w[i]);
}

// ---------------------------------------------------------------------------
// Implicit GEMM conv, double-buffered cp.async.
//   M=320 (2 tiles of 160), N=32768 (512 tiles of 64 = one (b,h) row), K=2880.
//   10 warps (5x2), warp tile 32x32, wmma m16n16k16 fp16->fp32.
// ---------------------------------------------------------------------------
#define APAD 8   // As row = 40 halfs = 80B
#define BPAD 8   // Bs row = 72 halfs = 144B
#define CPAD 8   // Cs row = 72 floats

struct LoadBufs {
    __half A[2][BM][BK + APAD];   // 25600 B
    __half B[2][BK][BN + BPAD];   //  9216 B
};

__global__ __launch_bounds__(NTHREADS, 2)
void conv_gemm_kernel(const float* __restrict__ scale,
                      const float* __restrict__ bias,
                      float* __restrict__ out)
{
    __shared__ __align__(16) unsigned char smem_raw[BM * (BN + CPAD) * 4]; // 46080 B >= sizeof(LoadBufs)
    LoadBufs* bufs = reinterpret_cast<LoadBufs*>(smem_raw);
    float (*Cs)[BN + CPAD] = reinterpret_cast<float (*)[BN + CPAD]>(smem_raw);

    const int tid  = threadIdx.x;            // 0..319
    const int warp = tid >> 5;               // 0..9
    const int wm   = (warp >> 1) * 32;       // 0,32,...,128
    const int wn   = (warp & 1) * 32;        // 0,32

    const int ntile = blockIdx.x;            // 0..511
    const int b  = ntile >> 6;
    const int h  = ntile & 63;
    const int m0 = blockIdx.y * BM;

    // ---- A load mapping: 640 uint4 (160 rows x 4 vecs) across 320 threads x2
    const int arow0 = tid >> 2;              // rows for v=0: 0..79
    const int acol0 = (tid & 3) * 8;
    // ---- B load mapping: 256 uint4 (32 rows x 8 vecs); threads 256..319 idle
    const int brow = tid >> 3;               // 0..39 (valid <32)
    const int bvec = tid & 7;

    uint32_t sA = (uint32_t)__cvta_generic_to_shared(&bufs->A[0][0][0]);
    uint32_t sB = (uint32_t)__cvta_generic_to_shared(&bufs->B[0][0][0]);
    const uint32_t stageA = BM * (BK + APAD) * 2;  // bytes per A stage
    const uint32_t stageB = BK * (BN + BPAD) * 2;  // bytes per B stage
    const uint32_t rowA   = (BK + APAD) * 2;
    const uint32_t rowB   = (BN + BPAD) * 2;

    auto load_stage = [&](int it, int buf) {
        int k0 = it * BK;
        // A tile: 160 x 32 halfs
        #pragma unroll
        for (int v = 0; v < 2; v++) {
            int row = arow0 + v * 80;
            const void* src = g_wh + (size_t)(m0 + row) * KTOT + k0 + acol0;
            cp_async16(sA + buf * stageA + row * rowA + acol0 * 2, src, 16);
        }
        // B tile: 32 x 64 halfs, rows contiguous in g_xq3 (pre-shifted)
        if (brow < BK) {
            int k  = k0 + brow;
            int ci = k / 9;
            int rr = k - ci * 9;
            int kh = rr / 3;
            int kw = rr - kh * 3;
            int ih = h + kh - 1;
            int ok = ((unsigned)ih < (unsigned)H_) ? 16 : 0;
            if (ok == 0) ih = 0;
            const void* src = g_xq3 +
                ((((size_t)b * CIN + ci) * H_ + ih) * 3 + kw) * W_ + bvec * 8;
            cp_async16(sB + buf * stageB + brow * rowB + bvec * 16, src, ok);
        }
        cp_commit();
    };

    wmma::fragment<wmma::accumulator, 16, 16, 16, float> acc[2][2];
    #pragma unroll
    for (int i = 0; i < 2; i++)
        #pragma unroll
        for (int j = 0; j < 2; j++)
            wmma::fill_fragment(acc[i][j], 0.0f);

    load_stage(0, 0);

    for (int it = 0; it < NK; it++) {
        cp_wait0();
        __syncthreads();
        if (it + 1 < NK) load_stage(it + 1, (it + 1) & 1);

        const int buf = it & 1;
        #pragma unroll
        for (int kk = 0; kk < BK; kk += 16) {
            wmma::fragment<wmma::matrix_a, 16, 16, 16, __half, wmma::row_major> af[2];
            wmma::fragment<wmma::matrix_b, 16, 16, 16, __half, wmma::row_major> bf[2];
            #pragma unroll
            for (int i = 0; i < 2; i++)
                wmma::load_matrix_sync(af[i], &bufs->A[buf][wm + 16 * i][kk], BK + APAD);
            #pragma unroll
            for (int j = 0; j < 2; j++)
                wmma::load_matrix_sync(bf[j], &bufs->B[buf][kk][wn + 16 * j], BN + BPAD);
            #pragma unroll
            for (int i = 0; i < 2; i++)
                #pragma unroll
                for (int j = 0; j < 2; j++)
                    wmma::mma_sync(acc[i][j], af[i], bf[j], acc[i][j]);
        }
        // next iteration's wait+sync protects buf before it is refilled
    }

    // ---- epilogue: accumulators -> smem (reusing load buffers) -> global
    __syncthreads();
    #pragma unroll
    for (int i = 0; i < 2; i++)
        #pragma unroll
        for (int j = 0; j < 2; j++)
            wmma::store_matrix_sync(&Cs[wm + 16 * i][wn + 16 * j], acc[i][j],
                                    BN + CPAD, wmma::mem_row_major);
    __syncthreads();

    const int w  = tid & 63;
    const int rg = tid >> 6;                 // 0..4
    #pragma unroll
    for (int j = 0; j < 32; j++) {
        int row = rg * 32 + j;
        int o   = m0 + row;
        out[(((size_t)b * COUT + o) * H_ + h) * W_ + w]
            = scale[o] * Cs[row][w] + bias[o];
    }
}

// ---------------------------------------------------------------------------
// Launch. Inputs (metadata order):
//   0: x [8,320,64,64] f32   1: weight_int [320,320,3,3] i32
//   2: weight_sum_by_ic (unused)  3: scale [320] f32
//   4: act_scales_inv [1] f32     5: act_zero_points [1] f32
//   6: bias [320] f32             out: f32 [8,320,64,64]
// ---------------------------------------------------------------------------
extern "C" void kernel_launch(void* const* d_in, const int* in_sizes, int n_in,
                              void* d_out, int out_size)
{
    const float* x    = (const float*)d_in[0];
    const int*   wint = (const int*)  d_in[1];
    const float* scl  = (const float*)d_in[3];
    const float* inv  = (const float*)d_in[4];
    const float* zp   = (const float*)d_in[5];
    const float* bias = (const float*)d_in[6];
    float* out = (float*)d_out;

    {   // quant + pre-shift: one warp per row, 8 warps per block
        int rows = B_ * CIN * H_;            // 163840
        int blocks = rows / 8;
        quant_kernel<<<blocks, 256>>>(x, inv, zp);
    }
    {   // weights -> fp16
        int n = COUT * KTOT;
        wconv_kernel<<<(n + 255) / 256, 256>>>(wint, n);
    }
    {   // main implicit GEMM
        dim3 grid(B_ * H_, COUT / BM);       // (512, 2)
        conv_gemm_kernel<<<grid, NTHREADS>>>(scl, bias, out);
    }
}